// round 15
// baseline (speedup 1.0000x reference)
#include <cuda_runtime.h>
#include <cuda_fp16.h>
#include <mma.h>

using namespace nvcuda;

#define NN 100000
#define NE 1600000
#define IND 75
#define H 64
#define HB 16

// Scratch (allocation-free rule: __device__ globals)
__device__ __align__(256) float  g_hA[NN * H];
__device__ __align__(256) float  g_hB[NN * H];
__device__ __align__(256) __half g_P[NN * H];
__device__ __align__(256) float  g_agg[NN * H];
__device__ __align__(256) __half g_eat16[(size_t)NE * HB];

// ---- f32x2 packed helpers -------------------------------------------------
typedef unsigned long long u64t;
__device__ __forceinline__ u64t pk2(float lo, float hi) {
    u64t r; asm("mov.b64 %0, {%1, %2};" : "=l"(r) : "f"(lo), "f"(hi)); return r;
}
__device__ __forceinline__ void upk2(u64t v, float& lo, float& hi) {
    asm("mov.b64 {%0, %1}, %2;" : "=f"(lo), "=f"(hi) : "l"(v));
}
__device__ __forceinline__ u64t fma2(u64t a, u64t b, u64t c) {
    u64t d; asm("fma.rn.f32x2 %0, %1, %2, %3;" : "=l"(d) : "l"(a), "l"(b), "l"(c)); return d;
}

// ---------------------------------------------------------------------------
// cvt: eattr fp32 -> fp16, once per launch
// ---------------------------------------------------------------------------
__global__ __launch_bounds__(256) void cvt_kernel(const float* __restrict__ e,
                                                  __half* __restrict__ o) {
    const size_t i = ((size_t)blockIdx.x * 256 + threadIdx.x) * 8;
    if (i >= (size_t)NE * HB) return;
    const float4 v0 = *(const float4*)(e + i);
    const float4 v1 = *(const float4*)(e + i + 4);
    __half2 h0 = __floats2half2_rn(v0.x, v0.y), h1 = __floats2half2_rn(v0.z, v0.w);
    __half2 h2 = __floats2half2_rn(v1.x, v1.y), h3 = __floats2half2_rn(v1.z, v1.w);
    uint4 p;
    p.x = *(unsigned*)&h0; p.y = *(unsigned*)&h1;
    p.z = *(unsigned*)&h2; p.w = *(unsigned*)&h3;
    *(uint4*)(o + i) = p;
}

// ---------------------------------------------------------------------------
// proj v2: out = x @ W(75x64) + b.  64-node tile, warp = 8 nodes, f32x2.
// ---------------------------------------------------------------------------
__global__ __launch_bounds__(256) void proj_kernel(const float* __restrict__ x,
                                                   const float* __restrict__ w,
                                                   const float* __restrict__ b,
                                                   float* __restrict__ out) {
    __shared__ float sW[IND * H];   // 19.2 KB linear
    __shared__ float sA[64 * IND];  // 19.2 KB linear
    for (int i = threadIdx.x; i < IND * H / 4; i += 256)
        *(float4*)&sW[i * 4] = *(const float4*)&w[i * 4];

    const int lane = threadIdx.x & 31, wid = threadIdx.x >> 5;
    const int nl = lane & 3, cg = lane >> 2;
    const int ln0 = (wid << 3) + (nl << 1), ln1 = ln0 + 1;
    const float4 bb0 = *(const float4*)&b[cg * 8];
    const float4 bb1 = *(const float4*)&b[cg * 8 + 4];
    const int ntiles = (NN + 63) / 64;

    for (int tile = blockIdx.x; tile < ntiles; tile += gridDim.x) {
        const int nbase = tile * 64;
        const int valid = (nbase + 64 <= NN) ? 64 : (NN - nbase);
        const int cnt4 = valid * IND / 4;
        __syncthreads();
        for (int i = threadIdx.x; i < cnt4; i += 256)
            *(float4*)&sA[i * 4] = *(const float4*)(x + (size_t)nbase * IND + i * 4);
        __syncthreads();

        u64t a0c[4] = {pk2(bb0.x, bb0.y), pk2(bb0.z, bb0.w),
                       pk2(bb1.x, bb1.y), pk2(bb1.z, bb1.w)};
        u64t a1c[4] = {a0c[0], a0c[1], a0c[2], a0c[3]};
#pragma unroll 5
        for (int k = 0; k < IND; k++) {
            const ulonglong2 w0 = *(const ulonglong2*)&sW[k * H + cg * 8];
            const ulonglong2 w1 = *(const ulonglong2*)&sW[k * H + cg * 8 + 4];
            const float a0 = sA[ln0 * IND + k];
            const float a1 = sA[ln1 * IND + k];
            const u64t aa0 = pk2(a0, a0), aa1 = pk2(a1, a1);
            a0c[0] = fma2(aa0, w0.x, a0c[0]); a0c[1] = fma2(aa0, w0.y, a0c[1]);
            a0c[2] = fma2(aa0, w1.x, a0c[2]); a0c[3] = fma2(aa0, w1.y, a0c[3]);
            a1c[0] = fma2(aa1, w0.x, a1c[0]); a1c[1] = fma2(aa1, w0.y, a1c[1]);
            a1c[2] = fma2(aa1, w1.x, a1c[2]); a1c[3] = fma2(aa1, w1.y, a1c[3]);
        }
#pragma unroll
        for (int n = 0; n < 2; n++) {
            const int gn = nbase + ((n == 0) ? ln0 : ln1);
            if (gn >= NN) continue;
            const u64t* ac = (n == 0) ? a0c : a1c;
            float f0, f1, f2, f3, f4, f5, f6, f7;
            upk2(ac[0], f0, f1); upk2(ac[1], f2, f3);
            upk2(ac[2], f4, f5); upk2(ac[3], f6, f7);
            float* op = out + (size_t)gn * H + cg * 8;
            *(float4*)op       = make_float4(f0, f1, f2, f3);
            *(float4*)(op + 4) = make_float4(f4, f5, f6, f7);
        }
    }
}

// ---------------------------------------------------------------------------
// pk v3: P(fp16) = h @ W2h(64x64) + b2, zero agg. 64-node tile.
// ---------------------------------------------------------------------------
__global__ __launch_bounds__(256) void pk_kernel(const float* __restrict__ h,
                                                 const float* __restrict__ w,
                                                 const float* __restrict__ b,
                                                 __half* __restrict__ P,
                                                 float* __restrict__ agg) {
    __shared__ float sW[H][H];       // 16 KB
    __shared__ float sA[64 * 64];    // 16 KB, swizzled
    for (int i = threadIdx.x; i < H * H; i += 256) sW[i >> 6][i & 63] = w[i];

    const int lane = threadIdx.x & 31, wid = threadIdx.x >> 5;
    const int nl = lane & 3, cg = lane >> 2;
    const int ln0 = (wid << 3) + (nl << 1), ln1 = ln0 + 1;
    const int sw0 = (ln0 & 7) * 4, sw1 = (ln1 & 7) * 4;
    const float4 bb0 = *(const float4*)&b[cg * 8];
    const float4 bb1 = *(const float4*)&b[cg * 8 + 4];

    const int snd = threadIdx.x >> 2, sq = threadIdx.x & 3;
    const int ntiles = (NN + 63) / 64;
    const float4 z4 = make_float4(0.f, 0.f, 0.f, 0.f);

    for (int tile = blockIdx.x; tile < ntiles; tile += gridDim.x) {
        const int nbase = tile * 64;
        __syncthreads();
        {
            const int gn = nbase + snd;
            const int ssw = (snd & 7) * 4;
            if (gn < NN) {
#pragma unroll
                for (int j = 0; j < 4; j++) {
                    const int kk = sq * 16 + j * 4;
                    float4 v = *(const float4*)(h + (size_t)gn * H + kk);
                    *(float4*)&sA[snd * 64 + (kk ^ ssw)] = v;
                }
            } else {
#pragma unroll
                for (int j = 0; j < 4; j++)
                    *(float4*)&sA[snd * 64 + ((sq * 16 + j * 4) ^ ssw)] = z4;
            }
        }
        __syncthreads();

        u64t a0c[4] = {pk2(bb0.x, bb0.y), pk2(bb0.z, bb0.w),
                       pk2(bb1.x, bb1.y), pk2(bb1.z, bb1.w)};
        u64t a1c[4] = {a0c[0], a0c[1], a0c[2], a0c[3]};
#pragma unroll 8
        for (int k = 0; k < H; k++) {
            const ulonglong2 w0 = *(const ulonglong2*)&sW[k][cg * 8];
            const ulonglong2 w1 = *(const ulonglong2*)&sW[k][cg * 8 + 4];
            const float a0 = sA[ln0 * 64 + (k ^ sw0)];
            const float a1 = sA[ln1 * 64 + (k ^ sw1)];
            const u64t aa0 = pk2(a0, a0), aa1 = pk2(a1, a1);
            a0c[0] = fma2(aa0, w0.x, a0c[0]); a0c[1] = fma2(aa0, w0.y, a0c[1]);
            a0c[2] = fma2(aa0, w1.x, a0c[2]); a0c[3] = fma2(aa0, w1.y, a0c[3]);
            a1c[0] = fma2(aa1, w0.x, a1c[0]); a1c[1] = fma2(aa1, w0.y, a1c[1]);
            a1c[2] = fma2(aa1, w1.x, a1c[2]); a1c[3] = fma2(aa1, w1.y, a1c[3]);
        }
#pragma unroll
        for (int n = 0; n < 2; n++) {
            const int gn = nbase + ((n == 0) ? ln0 : ln1);
            if (gn >= NN) continue;
            const u64t* ac = (n == 0) ? a0c : a1c;
            float f0, f1, f2, f3, f4, f5, f6, f7;
            upk2(ac[0], f0, f1); upk2(ac[1], f2, f3);
            upk2(ac[2], f4, f5); upk2(ac[3], f6, f7);
            __half2 p0 = __floats2half2_rn(f0, f1);
            __half2 p1 = __floats2half2_rn(f2, f3);
            __half2 p2 = __floats2half2_rn(f4, f5);
            __half2 p3 = __floats2half2_rn(f6, f7);
            uint4 pr;
            pr.x = *(unsigned*)&p0; pr.y = *(unsigned*)&p1;
            pr.z = *(unsigned*)&p2; pr.w = *(unsigned*)&p3;
            *(uint4*)(P + (size_t)gn * H + cg * 8) = pr;
        }
#pragma unroll
        for (int j = 0; j < 4; j++) {
            const int f = threadIdx.x * 4 + j;
            const int node = nbase + (f >> 4);
            if (node < NN)
                *((float4*)(agg + (size_t)nbase * H) + f) = z4;
        }
    }
}

// ---------------------------------------------------------------------------
// edge (HMMA, fp16 B tile): warp = 16 edges. fp16 eats -> wmma with HALF
// accumulator -> fp16 sB (half the smem churn, fewer regs) -> scatter
// agg[dst] +=red leakyrelu(P_fp16[src] + B_fp16).
// ---------------------------------------------------------------------------
__global__ __launch_bounds__(256) void edge_kernel(const int* __restrict__ esrc,
                                                   const int* __restrict__ edst,
                                                   const __half* __restrict__ eat16,
                                                   const float* __restrict__ w2e,
                                                   const __half* __restrict__ P,
                                                   float* __restrict__ agg) {
    __shared__ __half sW[HB * H];              // 2048 B
    __shared__ __half sA[8][HB * HB];          // 8 x 512 B
    __shared__ __half sB[8][HB * H];           // 8 x 2048 B (fp16)

    for (int i = threadIdx.x; i < HB * H; i += 256) sW[i] = __float2half(w2e[i]);
    __syncthreads();

    const int lane = threadIdx.x & 31, wid = threadIdx.x >> 5;
    const int half = lane >> 4, hl = lane & 15;
    const int cbase = hl * 4;

    wmma::fragment<wmma::matrix_b, 16, 16, 16, __half, wmma::row_major> fw[4];
#pragma unroll
    for (int nt = 0; nt < 4; nt++)
        wmma::load_matrix_sync(fw[nt], &sW[nt * 16], H);

    __half* const myA = sA[wid];
    __half* const myB = sB[wid];

    const int gw = blockIdx.x * 8 + wid;
    const int nw = gridDim.x * 8;

    for (int t = gw; t < NE / 16; t += nw) {
        const int ebase = t * 16;
        // stage 16x16 fp16 tile: one coalesced 512B span per warp
        *(uint4*)(myA + lane * 8) =
            *(const uint4*)(eat16 + (size_t)ebase * HB + lane * 8);
        __syncwarp();

        wmma::fragment<wmma::matrix_a, 16, 16, 16, __half, wmma::row_major> fa;
        wmma::load_matrix_sync(fa, myA, HB);
#pragma unroll
        for (int nt = 0; nt < 4; nt++) {
            wmma::fragment<wmma::accumulator, 16, 16, 16, __half> fc;
            wmma::fill_fragment(fc, __float2half(0.f));
            wmma::mma_sync(fc, fa, fw[nt], fc);
            wmma::store_matrix_sync(&myB[nt * 16], fc, H, wmma::mem_row_major);
        }
        __syncwarp();

#pragma unroll
        for (int r = 0; r < 8; r++) {
            const int el = 2 * r + half;
            const int e = ebase + el;
            const int src = esrc[e];
            const int dst = edst[e];
            if ((unsigned)src >= NN || (unsigned)dst >= NN) continue;

            const uint2 braw = *(const uint2*)(myB + el * H + cbase);
            const float2 ba = __half22float2(*(const __half2*)&braw.x);
            const float2 bb = __half22float2(*(const __half2*)&braw.y);
            const uint2 praw = *(const uint2*)(P + (size_t)src * H + cbase);
            const float2 pa = __half22float2(*(const __half2*)&praw.x);
            const float2 pb = __half22float2(*(const __half2*)&praw.y);

            float m0 = pa.x + ba.x, m1 = pa.y + ba.y;
            float m2 = pb.x + bb.x, m3 = pb.y + bb.y;
            m0 = fmaxf(m0, 0.1f * m0);
            m1 = fmaxf(m1, 0.1f * m1);
            m2 = fmaxf(m2, 0.1f * m2);
            m3 = fmaxf(m3, 0.1f * m3);

            float* dp = agg + (size_t)dst * H + cbase;
            asm volatile("red.global.add.v4.f32 [%0], {%1, %2, %3, %4};"
                         :: "l"(dp), "f"(m0), "f"(m1), "f"(m2), "f"(m3)
                         : "memory");
        }
        __syncwarp();
    }
}

// ---------------------------------------------------------------------------
// upd v3: out = concat(h, agg) @ W1(128x64) + b1. 64-node tile.
// ---------------------------------------------------------------------------
__global__ __launch_bounds__(256) void upd_kernel(const float* __restrict__ h,
                                                  const float* __restrict__ agg,
                                                  const float* __restrict__ w,
                                                  const float* __restrict__ b,
                                                  float* __restrict__ out) {
    __shared__ float sW[2 * H][H];   // 32 KB
    __shared__ float sA[64 * 64];    // 16 KB, swizzled
    for (int i = threadIdx.x; i < 2 * H * H; i += 256) sW[i >> 6][i & 63] = w[i];

    const int lane = threadIdx.x & 31, wid = threadIdx.x >> 5;
    const int nl = lane & 3, cg = lane >> 2;
    const int ln0 = (wid << 3) + (nl << 1), ln1 = ln0 + 1;
    const int sw0 = (ln0 & 7) * 4, sw1 = (ln1 & 7) * 4;
    const float4 bb0 = *(const float4*)&b[cg * 8];
    const float4 bb1 = *(const float4*)&b[cg * 8 + 4];

    const int snd = threadIdx.x >> 2, sq = threadIdx.x & 3;
    const int ntiles = (NN + 63) / 64;
    const float4 z4 = make_float4(0.f, 0.f, 0.f, 0.f);

    for (int tile = blockIdx.x; tile < ntiles; tile += gridDim.x) {
        const int nbase = tile * 64;
        u64t a0c[4] = {pk2(bb0.x, bb0.y), pk2(bb0.z, bb0.w),
                       pk2(bb1.x, bb1.y), pk2(bb1.z, bb1.w)};
        u64t a1c[4] = {a0c[0], a0c[1], a0c[2], a0c[3]};

#pragma unroll
        for (int ch = 0; ch < 2; ch++) {
            const float* srcm = (ch == 0) ? h : agg;
            __syncthreads();
            {
                const int gn = nbase + snd;
                const int ssw = (snd & 7) * 4;
                if (gn < NN) {
#pragma unroll
                    for (int j = 0; j < 4; j++) {
                        const int kk = sq * 16 + j * 4;
                        float4 v = *(const float4*)(srcm + (size_t)gn * H + kk);
                        *(float4*)&sA[snd * 64 + (kk ^ ssw)] = v;
                    }
                } else {
#pragma unroll
                    for (int j = 0; j < 4; j++)
                        *(float4*)&sA[snd * 64 + ((sq * 16 + j * 4) ^ ssw)] = z4;
                }
            }
            __syncthreads();

#pragma unroll 8
            for (int k = 0; k < H; k++) {
                const int wrow = ch * H + k;
                const ulonglong2 w0 = *(const ulonglong2*)&sW[wrow][cg * 8];
                const ulonglong2 w1 = *(const ulonglong2*)&sW[wrow][cg * 8 + 4];
                const float a0 = sA[ln0 * 64 + (k ^ sw0)];
                const float a1 = sA[ln1 * 64 + (k ^ sw1)];
                const u64t aa0 = pk2(a0, a0), aa1 = pk2(a1, a1);
                a0c[0] = fma2(aa0, w0.x, a0c[0]); a0c[1] = fma2(aa0, w0.y, a0c[1]);
                a0c[2] = fma2(aa0, w1.x, a0c[2]); a0c[3] = fma2(aa0, w1.y, a0c[3]);
                a1c[0] = fma2(aa1, w0.x, a1c[0]); a1c[1] = fma2(aa1, w0.y, a1c[1]);
                a1c[2] = fma2(aa1, w1.x, a1c[2]); a1c[3] = fma2(aa1, w1.y, a1c[3]);
            }
        }

#pragma unroll
        for (int n = 0; n < 2; n++) {
            const int gn = nbase + ((n == 0) ? ln0 : ln1);
            if (gn >= NN) continue;
            const u64t* ac = (n == 0) ? a0c : a1c;
            float f0, f1, f2, f3, f4, f5, f6, f7;
            upk2(ac[0], f0, f1); upk2(ac[1], f2, f3);
            upk2(ac[2], f4, f5); upk2(ac[3], f6, f7);
            float* op = out + (size_t)gn * H + cg * 8;
            *(float4*)op       = make_float4(f0, f1, f2, f3);
            *(float4*)(op + 4) = make_float4(f4, f5, f6, f7);
        }
    }
}

// ---------------------------------------------------------------------------
extern "C" void kernel_launch(void* const* d_in, const int* in_sizes, int n_in,
                              void* d_out, int out_size) {
    const float* x      = (const float*)d_in[0];   // [100000, 75]
    const int*   eidx   = (const int*)d_in[1];     // [2, 1600000] (int64 -> int32)
    const float* eattr  = (const float*)d_in[2];   // [1600000, 16]
    const float* proj_w = (const float*)d_in[3];
    const float* proj_b = (const float*)d_in[4];
    const float* u2w    = (const float*)d_in[5];   // [3, 80, 64]
    const float* u2b    = (const float*)d_in[6];
    const float* u1w    = (const float*)d_in[7];   // [3, 128, 64]
    const float* u1b    = (const float*)d_in[8];
    float*       out    = (float*)d_out;           // [100000, 64]

    float *hA, *hB, *agg;
    __half *P, *eat16;
    cudaGetSymbolAddress((void**)&hA, g_hA);
    cudaGetSymbolAddress((void**)&hB, g_hB);
    cudaGetSymbolAddress((void**)&P, g_P);
    cudaGetSymbolAddress((void**)&agg, g_agg);
    cudaGetSymbolAddress((void**)&eat16, g_eat16);

    cvt_kernel<<<(NE * HB / 8 + 255) / 256, 256>>>(eattr, eat16);
    proj_kernel<<<592, 256>>>(x, proj_w, proj_b, hA);

    for (int l = 0; l < 3; l++) {
        const float* hin = (l == 1) ? hB : hA;          // l0:A, l1:B, l2:A
        float* hout = (l == 0) ? hB : ((l == 1) ? hA : out);
        const float* w2 = u2w + (size_t)l * 80 * 64;     // rows 0..63 = W2h, 64..79 = W2e
        pk_kernel<<<592, 256>>>(hin, w2, u2b + l * 64, P, agg);
        edge_kernel<<<1184, 256>>>(eidx, eidx + NE, eat16, w2 + 64 * 64, P, agg);
        upd_kernel<<<592, 256>>>(hin, agg, u1w + (size_t)l * 128 * 64, u1b + l * 64, hout);
    }
}

// round 16
// speedup vs baseline: 1.0211x; 1.0211x over previous
#include <cuda_runtime.h>
#include <cuda_fp16.h>
#include <mma.h>

using namespace nvcuda;

#define NN 100000
#define NE 1600000
#define IND 75
#define H 64
#define HB 16

// Scratch (allocation-free rule: __device__ globals)
__device__ __align__(256) float  g_hA[NN * H];
__device__ __align__(256) float  g_hB[NN * H];
__device__ __align__(256) __half g_P[NN * H];
__device__ __align__(256) float  g_agg[NN * H];
__device__ __align__(256) __half g_eat16[(size_t)NE * HB];

// ---- f32x2 packed helpers -------------------------------------------------
typedef unsigned long long u64t;
__device__ __forceinline__ u64t pk2(float lo, float hi) {
    u64t r; asm("mov.b64 %0, {%1, %2};" : "=l"(r) : "f"(lo), "f"(hi)); return r;
}
__device__ __forceinline__ void upk2(u64t v, float& lo, float& hi) {
    asm("mov.b64 {%0, %1}, %2;" : "=f"(lo), "=f"(hi) : "l"(v));
}
__device__ __forceinline__ u64t fma2(u64t a, u64t b, u64t c) {
    u64t d; asm("fma.rn.f32x2 %0, %1, %2, %3;" : "=l"(d) : "l"(a), "l"(b), "l"(c)); return d;
}

// W-pair smem layout: row kp holds 128 floats; (c, parity) at
//   j*32 + cg*4 + (cj&1)*2 + parity   where cg=c>>3, cj=c&7, j=cj>>1.
// Lane with col-group cg reads 4x ulonglong2 at {kp*128 + j*32 + cg*4},
// j=0..3 — for fixed j all 8 cg land in ONE 128B line -> conflict-free.
__device__ __forceinline__ int wpair_idx(int k, int c) {
    const int kp = k >> 1, par = k & 1, cg = c >> 3, cj = c & 7, j = cj >> 1;
    return kp * 128 + j * 32 + cg * 4 + (cj & 1) * 2 + par;
}

// ---------------------------------------------------------------------------
// cvt: eattr fp32 -> fp16, once per launch
// ---------------------------------------------------------------------------
__global__ __launch_bounds__(256) void cvt_kernel(const float* __restrict__ e,
                                                  __half* __restrict__ o) {
    const size_t i = ((size_t)blockIdx.x * 256 + threadIdx.x) * 8;
    if (i >= (size_t)NE * HB) return;
    const float4 v0 = *(const float4*)(e + i);
    const float4 v1 = *(const float4*)(e + i + 4);
    __half2 h0 = __floats2half2_rn(v0.x, v0.y), h1 = __floats2half2_rn(v0.z, v0.w);
    __half2 h2 = __floats2half2_rn(v1.x, v1.y), h3 = __floats2half2_rn(v1.z, v1.w);
    uint4 p;
    p.x = *(unsigned*)&h0; p.y = *(unsigned*)&h1;
    p.z = *(unsigned*)&h2; p.w = *(unsigned*)&h3;
    *(uint4*)(o + i) = p;
}

// ---------------------------------------------------------------------------
// proj v2 (R14): out = x @ W(75x64) + b.  64-node tile, warp = 8 nodes, f32x2.
// ---------------------------------------------------------------------------
__global__ __launch_bounds__(256) void proj_kernel(const float* __restrict__ x,
                                                   const float* __restrict__ w,
                                                   const float* __restrict__ b,
                                                   float* __restrict__ out) {
    __shared__ float sW[IND * H];   // 19.2 KB linear
    __shared__ float sA[64 * IND];  // 19.2 KB linear
    for (int i = threadIdx.x; i < IND * H / 4; i += 256)
        *(float4*)&sW[i * 4] = *(const float4*)&w[i * 4];

    const int lane = threadIdx.x & 31, wid = threadIdx.x >> 5;
    const int nl = lane & 3, cg = lane >> 2;
    const int ln0 = (wid << 3) + (nl << 1), ln1 = ln0 + 1;
    const float4 bb0 = *(const float4*)&b[cg * 8];
    const float4 bb1 = *(const float4*)&b[cg * 8 + 4];
    const int ntiles = (NN + 63) / 64;

    for (int tile = blockIdx.x; tile < ntiles; tile += gridDim.x) {
        const int nbase = tile * 64;
        const int valid = (nbase + 64 <= NN) ? 64 : (NN - nbase);
        const int cnt4 = valid * IND / 4;
        __syncthreads();
        for (int i = threadIdx.x; i < cnt4; i += 256)
            *(float4*)&sA[i * 4] = *(const float4*)(x + (size_t)nbase * IND + i * 4);
        __syncthreads();

        u64t a0c[4] = {pk2(bb0.x, bb0.y), pk2(bb0.z, bb0.w),
                       pk2(bb1.x, bb1.y), pk2(bb1.z, bb1.w)};
        u64t a1c[4] = {a0c[0], a0c[1], a0c[2], a0c[3]};
#pragma unroll 5
        for (int k = 0; k < IND; k++) {
            const ulonglong2 w0 = *(const ulonglong2*)&sW[k * H + cg * 8];
            const ulonglong2 w1 = *(const ulonglong2*)&sW[k * H + cg * 8 + 4];
            const float a0 = sA[ln0 * IND + k];
            const float a1 = sA[ln1 * IND + k];
            const u64t aa0 = pk2(a0, a0), aa1 = pk2(a1, a1);
            a0c[0] = fma2(aa0, w0.x, a0c[0]); a0c[1] = fma2(aa0, w0.y, a0c[1]);
            a0c[2] = fma2(aa0, w1.x, a0c[2]); a0c[3] = fma2(aa0, w1.y, a0c[3]);
            a1c[0] = fma2(aa1, w0.x, a1c[0]); a1c[1] = fma2(aa1, w0.y, a1c[1]);
            a1c[2] = fma2(aa1, w1.x, a1c[2]); a1c[3] = fma2(aa1, w1.y, a1c[3]);
        }
#pragma unroll
        for (int n = 0; n < 2; n++) {
            const int gn = nbase + ((n == 0) ? ln0 : ln1);
            if (gn >= NN) continue;
            const u64t* ac = (n == 0) ? a0c : a1c;
            float f0, f1, f2, f3, f4, f5, f6, f7;
            upk2(ac[0], f0, f1); upk2(ac[1], f2, f3);
            upk2(ac[2], f4, f5); upk2(ac[3], f6, f7);
            float* op = out + (size_t)gn * H + cg * 8;
            *(float4*)op       = make_float4(f0, f1, f2, f3);
            *(float4*)(op + 4) = make_float4(f4, f5, f6, f7);
        }
    }
}

// ---------------------------------------------------------------------------
// pk v4 (even/odd K-pairs): P(fp16) = h @ W2h(64x64) + b2, zero agg.
// 64-node tile, warp = 8 nodes; per-2k: 1 LDS.64/node + 4 LDS.128 W + 16 fma2,
// zero pack movs.
// ---------------------------------------------------------------------------
__global__ __launch_bounds__(256) void pk_kernel(const float* __restrict__ h,
                                                 const float* __restrict__ w,
                                                 const float* __restrict__ b,
                                                 __half* __restrict__ P,
                                                 float* __restrict__ agg) {
    __shared__ float sW2[(H / 2) * 128];  // 16 KB pair-packed
    __shared__ float sA[64 * 64];         // 16 KB, swizzled
    for (int i = threadIdx.x; i < H * H; i += 256)
        sW2[wpair_idx(i >> 6, i & 63)] = w[i];

    const int lane = threadIdx.x & 31, wid = threadIdx.x >> 5;
    const int nl = lane & 3, cg = lane >> 2;
    const int ln0 = (wid << 3) + (nl << 1), ln1 = ln0 + 1;
    const int sw0 = (ln0 & 7) * 4, sw1 = (ln1 & 7) * 4;
    float bias[8];
#pragma unroll
    for (int c = 0; c < 8; c++) bias[c] = b[cg * 8 + c];

    const int snd = threadIdx.x >> 2, sq = threadIdx.x & 3;
    const int ntiles = (NN + 63) / 64;
    const float4 z4 = make_float4(0.f, 0.f, 0.f, 0.f);

    for (int tile = blockIdx.x; tile < ntiles; tile += gridDim.x) {
        const int nbase = tile * 64;
        __syncthreads();
        {
            const int gn = nbase + snd;
            const int ssw = (snd & 7) * 4;
            if (gn < NN) {
#pragma unroll
                for (int j = 0; j < 4; j++) {
                    const int kk = sq * 16 + j * 4;
                    float4 v = *(const float4*)(h + (size_t)gn * H + kk);
                    *(float4*)&sA[snd * 64 + (kk ^ ssw)] = v;
                }
            } else {
#pragma unroll
                for (int j = 0; j < 4; j++)
                    *(float4*)&sA[snd * 64 + ((sq * 16 + j * 4) ^ ssw)] = z4;
            }
        }
        __syncthreads();

        u64t acc0[8], acc1[8];
#pragma unroll
        for (int c = 0; c < 8; c++) {
            acc0[c] = pk2(bias[c], 0.f);
            acc1[c] = pk2(bias[c], 0.f);
        }
#pragma unroll 8
        for (int kp = 0; kp < H / 2; kp++) {
            const float* wr = &sW2[kp * 128 + cg * 4];
            const ulonglong2 wa = *(const ulonglong2*)(wr);
            const ulonglong2 wb = *(const ulonglong2*)(wr + 32);
            const ulonglong2 wc = *(const ulonglong2*)(wr + 64);
            const ulonglong2 wd = *(const ulonglong2*)(wr + 96);
            const u64t ap0 = *(const u64t*)&sA[ln0 * 64 + ((2 * kp) ^ sw0)];
            const u64t ap1 = *(const u64t*)&sA[ln1 * 64 + ((2 * kp) ^ sw1)];
            acc0[0] = fma2(ap0, wa.x, acc0[0]); acc0[1] = fma2(ap0, wa.y, acc0[1]);
            acc0[2] = fma2(ap0, wb.x, acc0[2]); acc0[3] = fma2(ap0, wb.y, acc0[3]);
            acc0[4] = fma2(ap0, wc.x, acc0[4]); acc0[5] = fma2(ap0, wc.y, acc0[5]);
            acc0[6] = fma2(ap0, wd.x, acc0[6]); acc0[7] = fma2(ap0, wd.y, acc0[7]);
            acc1[0] = fma2(ap1, wa.x, acc1[0]); acc1[1] = fma2(ap1, wa.y, acc1[1]);
            acc1[2] = fma2(ap1, wb.x, acc1[2]); acc1[3] = fma2(ap1, wb.y, acc1[3]);
            acc1[4] = fma2(ap1, wc.x, acc1[4]); acc1[5] = fma2(ap1, wc.y, acc1[5]);
            acc1[6] = fma2(ap1, wd.x, acc1[6]); acc1[7] = fma2(ap1, wd.y, acc1[7]);
        }
#pragma unroll
        for (int n = 0; n < 2; n++) {
            const int gn = nbase + ((n == 0) ? ln0 : ln1);
            if (gn >= NN) continue;
            const u64t* ac = (n == 0) ? acc0 : acc1;
            float f[8];
#pragma unroll
            for (int c = 0; c < 8; c++) {
                float lo, hi; upk2(ac[c], lo, hi); f[c] = lo + hi;
            }
            __half2 p0 = __floats2half2_rn(f[0], f[1]);
            __half2 p1 = __floats2half2_rn(f[2], f[3]);
            __half2 p2 = __floats2half2_rn(f[4], f[5]);
            __half2 p3 = __floats2half2_rn(f[6], f[7]);
            uint4 pr;
            pr.x = *(unsigned*)&p0; pr.y = *(unsigned*)&p1;
            pr.z = *(unsigned*)&p2; pr.w = *(unsigned*)&p3;
            *(uint4*)(P + (size_t)gn * H + cg * 8) = pr;
        }
#pragma unroll
        for (int j = 0; j < 4; j++) {
            const int f = threadIdx.x * 4 + j;
            const int node = nbase + (f >> 4);
            if (node < NN)
                *((float4*)(agg + (size_t)nbase * H) + f) = z4;
        }
    }
}

// ---------------------------------------------------------------------------
// edge (R14, best measured): warp = 16 edges; fp16 eats -> wmma (fp32 acc) vs
// reg-resident W2e -> fp32 sB -> scatter agg[dst] +=red leakyrelu(P+B).
// ---------------------------------------------------------------------------
__global__ __launch_bounds__(256) void edge_kernel(const int* __restrict__ esrc,
                                                   const int* __restrict__ edst,
                                                   const __half* __restrict__ eat16,
                                                   const float* __restrict__ w2e,
                                                   const __half* __restrict__ P,
                                                   float* __restrict__ agg) {
    __shared__ __half sW[HB * H];              // 2048 B
    __shared__ __half sA[8][HB * HB];          // 8 x 512 B
    __shared__ float  sB[8][HB * H];           // 8 x 4096 B

    for (int i = threadIdx.x; i < HB * H; i += 256) sW[i] = __float2half(w2e[i]);
    __syncthreads();

    const int lane = threadIdx.x & 31, wid = threadIdx.x >> 5;
    const int half = lane >> 4, hl = lane & 15;
    const int cbase = hl * 4;

    wmma::fragment<wmma::matrix_b, 16, 16, 16, __half, wmma::row_major> fw[4];
#pragma unroll
    for (int nt = 0; nt < 4; nt++)
        wmma::load_matrix_sync(fw[nt], &sW[nt * 16], H);

    __half* const myA = sA[wid];
    float*  const myB = sB[wid];

    const int gw = blockIdx.x * 8 + wid;
    const int nw = gridDim.x * 8;

    for (int t = gw; t < NE / 16; t += nw) {
        const int ebase = t * 16;
        *(uint4*)(myA + lane * 8) =
            *(const uint4*)(eat16 + (size_t)ebase * HB + lane * 8);
        __syncwarp();

        wmma::fragment<wmma::matrix_a, 16, 16, 16, __half, wmma::row_major> fa;
        wmma::load_matrix_sync(fa, myA, HB);
#pragma unroll
        for (int nt = 0; nt < 4; nt++) {
            wmma::fragment<wmma::accumulator, 16, 16, 16, float> fc;
            wmma::fill_fragment(fc, 0.f);
            wmma::mma_sync(fc, fa, fw[nt], fc);
            wmma::store_matrix_sync(&myB[nt * 16], fc, H, wmma::mem_row_major);
        }
        __syncwarp();

#pragma unroll
        for (int r = 0; r < 8; r++) {
            const int el = 2 * r + half;
            const int e = ebase + el;
            const int src = esrc[e];
            const int dst = edst[e];
            if ((unsigned)src >= NN || (unsigned)dst >= NN) continue;

            const float4 bv = *(const float4*)(myB + el * H + cbase);
            const uint2 praw = *(const uint2*)(P + (size_t)src * H + cbase);
            const float2 pa = __half22float2(*(const __half2*)&praw.x);
            const float2 pb = __half22float2(*(const __half2*)&praw.y);

            float m0 = pa.x + bv.x, m1 = pa.y + bv.y;
            float m2 = pb.x + bv.z, m3 = pb.y + bv.w;
            m0 = fmaxf(m0, 0.1f * m0);
            m1 = fmaxf(m1, 0.1f * m1);
            m2 = fmaxf(m2, 0.1f * m2);
            m3 = fmaxf(m3, 0.1f * m3);

            float* dp = agg + (size_t)dst * H + cbase;
            asm volatile("red.global.add.v4.f32 [%0], {%1, %2, %3, %4};"
                         :: "l"(dp), "f"(m0), "f"(m1), "f"(m2), "f"(m3)
                         : "memory");
        }
        __syncwarp();
    }
}

// ---------------------------------------------------------------------------
// upd v4 (even/odd K-pairs): out = concat(h, agg) @ W1(128x64) + b1.
// 64-node tile, warp = 8 nodes; K=128 in two 64-col chunks.
// smem: sW2 32KB + sA 16KB = 48KB.
// ---------------------------------------------------------------------------
__global__ __launch_bounds__(256) void upd_kernel(const float* __restrict__ h,
                                                  const float* __restrict__ agg,
                                                  const float* __restrict__ w,
                                                  const float* __restrict__ b,
                                                  float* __restrict__ out) {
    __shared__ float sW2[H * 128];   // 64 kp-rows x 128 = 32 KB pair-packed
    __shared__ float sA[64 * 64];    // 16 KB, swizzled
    for (int i = threadIdx.x; i < 2 * H * H; i += 256)
        sW2[wpair_idx(i >> 6, i & 63)] = w[i];

    const int lane = threadIdx.x & 31, wid = threadIdx.x >> 5;
    const int nl = lane & 3, cg = lane >> 2;
    const int ln0 = (wid << 3) + (nl << 1), ln1 = ln0 + 1;
    const int sw0 = (ln0 & 7) * 4, sw1 = (ln1 & 7) * 4;
    float bias[8];
#pragma unroll
    for (int c = 0; c < 8; c++) bias[c] = b[cg * 8 + c];

    const int snd = threadIdx.x >> 2, sq = threadIdx.x & 3;
    const int ntiles = (NN + 63) / 64;
    const float4 z4 = make_float4(0.f, 0.f, 0.f, 0.f);

    for (int tile = blockIdx.x; tile < ntiles; tile += gridDim.x) {
        const int nbase = tile * 64;
        u64t acc0[8], acc1[8];
#pragma unroll
        for (int c = 0; c < 8; c++) {
            acc0[c] = pk2(bias[c], 0.f);
            acc1[c] = pk2(bias[c], 0.f);
        }

#pragma unroll
        for (int ch = 0; ch < 2; ch++) {
            const float* srcm = (ch == 0) ? h : agg;
            __syncthreads();
            {
                const int gn = nbase + snd;
                const int ssw = (snd & 7) * 4;
                if (gn < NN) {
#pragma unroll
                    for (int j = 0; j < 4; j++) {
                        const int kk = sq * 16 + j * 4;
                        float4 v = *(const float4*)(srcm + (size_t)gn * H + kk);
                        *(float4*)&sA[snd * 64 + (kk ^ ssw)] = v;
                    }
                } else {
#pragma unroll
                    for (int j = 0; j < 4; j++)
                        *(float4*)&sA[snd * 64 + ((sq * 16 + j * 4) ^ ssw)] = z4;
                }
            }
            __syncthreads();

            const float* wbase = &sW2[(ch * (H / 2)) * 128 + cg * 4];
#pragma unroll 8
            for (int kp = 0; kp < H / 2; kp++) {
                const float* wr = wbase + kp * 128;
                const ulonglong2 wa = *(const ulonglong2*)(wr);
                const ulonglong2 wb = *(const ulonglong2*)(wr + 32);
                const ulonglong2 wc = *(const ulonglong2*)(wr + 64);
                const ulonglong2 wd = *(const ulonglong2*)(wr + 96);
                const u64t ap0 = *(const u64t*)&sA[ln0 * 64 + ((2 * kp) ^ sw0)];
                const u64t ap1 = *(const u64t*)&sA[ln1 * 64 + ((2 * kp) ^ sw1)];
                acc0[0] = fma2(ap0, wa.x, acc0[0]); acc0[1] = fma2(ap0, wa.y, acc0[1]);
                acc0[2] = fma2(ap0, wb.x, acc0[2]); acc0[3] = fma2(ap0, wb.y, acc0[3]);
                acc0[4] = fma2(ap0, wc.x, acc0[4]); acc0[5] = fma2(ap0, wc.y, acc0[5]);
                acc0[6] = fma2(ap0, wd.x, acc0[6]); acc0[7] = fma2(ap0, wd.y, acc0[7]);
                acc1[0] = fma2(ap1, wa.x, acc1[0]); acc1[1] = fma2(ap1, wa.y, acc1[1]);
                acc1[2] = fma2(ap1, wb.x, acc1[2]); acc1[3] = fma2(ap1, wb.y, acc1[3]);
                acc1[4] = fma2(ap1, wc.x, acc1[4]); acc1[5] = fma2(ap1, wc.y, acc1[5]);
                acc1[6] = fma2(ap1, wd.x, acc1[6]); acc1[7] = fma2(ap1, wd.y, acc1[7]);
            }
        }

#pragma unroll
        for (int n = 0; n < 2; n++) {
            const int gn = nbase + ((n == 0) ? ln0 : ln1);
            if (gn >= NN) continue;
            const u64t* ac = (n == 0) ? acc0 : acc1;
            float f[8];
#pragma unroll
            for (int c = 0; c < 8; c++) {
                float lo, hi; upk2(ac[c], lo, hi); f[c] = lo + hi;
            }
            float* op = out + (size_t)gn * H + cg * 8;
            *(float4*)op       = make_float4(f[0], f[1], f[2], f[3]);
            *(float4*)(op + 4) = make_float4(f[4], f[5], f[6], f[7]);
        }
    }
}

// ---------------------------------------------------------------------------
extern "C" void kernel_launch(void* const* d_in, const int* in_sizes, int n_in,
                              void* d_out, int out_size) {
    const float* x      = (const float*)d_in[0];   // [100000, 75]
    const int*   eidx   = (const int*)d_in[1];     // [2, 1600000] (int64 -> int32)
    const float* eattr  = (const float*)d_in[2];   // [1600000, 16]
    const float* proj_w = (const float*)d_in[3];
    const float* proj_b = (const float*)d_in[4];
    const float* u2w    = (const float*)d_in[5];   // [3, 80, 64]
    const float* u2b    = (const float*)d_in[6];
    const float* u1w    = (const float*)d_in[7];   // [3, 128, 64]
    const float* u1b    = (const float*)d_in[8];
    float*       out    = (float*)d_out;           // [100000, 64]

    float *hA, *hB, *agg;
    __half *P, *eat16;
    cudaGetSymbolAddress((void**)&hA, g_hA);
    cudaGetSymbolAddress((void**)&hB, g_hB);
    cudaGetSymbolAddress((void**)&P, g_P);
    cudaGetSymbolAddress((void**)&agg, g_agg);
    cudaGetSymbolAddress((void**)&eat16, g_eat16);

    cvt_kernel<<<(NE * HB / 8 + 255) / 256, 256>>>(eattr, eat16);
    proj_kernel<<<592, 256>>>(x, proj_w, proj_b, hA);

    for (int l = 0; l < 3; l++) {
        const float* hin = (l == 1) ? hB : hA;          // l0:A, l1:B, l2:A
        float* hout = (l == 0) ? hB : ((l == 1) ? hA : out);
        const float* w2 = u2w + (size_t)l * 80 * 64;     // rows 0..63 = W2h, 64..79 = W2e
        pk_kernel<<<592, 256>>>(hin, w2, u2b + l * 64, P, agg);
        edge_kernel<<<1184, 256>>>(eidx, eidx + NE, eat16, w2 + 64 * 64, P, agg);
        upd_kernel<<<592, 256>>>(hin, agg, u1w + (size_t)l * 128 * 64, u1b + l * 64, hout);
    }
}

// round 17
// speedup vs baseline: 1.0457x; 1.0241x over previous
#include <cuda_runtime.h>
#include <cuda_fp16.h>
#include <mma.h>

using namespace nvcuda;

#define NN 100000
#define NE 1600000
#define IND 75
#define H 64
#define HB 16

// Scratch (allocation-free rule: __device__ globals)
__device__ __align__(256) float  g_hA[NN * H];
__device__ __align__(256) float  g_hB[NN * H];
__device__ __align__(256) __half g_P[NN * H];
__device__ __align__(256) float  g_agg[NN * H];
__device__ __align__(256) __half g_eat16[(size_t)NE * HB];

// ---- f32x2 packed helpers -------------------------------------------------
typedef unsigned long long u64t;
__device__ __forceinline__ u64t pk2(float lo, float hi) {
    u64t r; asm("mov.b64 %0, {%1, %2};" : "=l"(r) : "f"(lo), "f"(hi)); return r;
}
__device__ __forceinline__ void upk2(u64t v, float& lo, float& hi) {
    asm("mov.b64 {%0, %1}, %2;" : "=f"(lo), "=f"(hi) : "l"(v));
}
__device__ __forceinline__ u64t fma2(u64t a, u64t b, u64t c) {
    u64t d; asm("fma.rn.f32x2 %0, %1, %2, %3;" : "=l"(d) : "l"(a), "l"(b), "l"(c)); return d;
}

// W-pair smem layout (see R16): row kp holds 128 floats; conflict-free LDS.128.
__device__ __forceinline__ int wpair_idx(int k, int c) {
    const int kp = k >> 1, par = k & 1, cg = c >> 3, cj = c & 7, j = cj >> 1;
    return kp * 128 + j * 32 + cg * 4 + (cj & 1) * 2 + par;
}

// ---------------------------------------------------------------------------
// cvt: eattr fp32 -> fp16, once per launch
// ---------------------------------------------------------------------------
__global__ __launch_bounds__(256) void cvt_kernel(const float* __restrict__ e,
                                                  __half* __restrict__ o) {
    const size_t i = ((size_t)blockIdx.x * 256 + threadIdx.x) * 8;
    if (i >= (size_t)NE * HB) return;
    const float4 v0 = *(const float4*)(e + i);
    const float4 v1 = *(const float4*)(e + i + 4);
    __half2 h0 = __floats2half2_rn(v0.x, v0.y), h1 = __floats2half2_rn(v0.z, v0.w);
    __half2 h2 = __floats2half2_rn(v1.x, v1.y), h3 = __floats2half2_rn(v1.z, v1.w);
    uint4 p;
    p.x = *(unsigned*)&h0; p.y = *(unsigned*)&h1;
    p.z = *(unsigned*)&h2; p.w = *(unsigned*)&h3;
    *(uint4*)(o + i) = p;
}

// ---------------------------------------------------------------------------
// proj v2: out = x @ W(75x64) + b.  64-node tile, warp = 8 nodes, f32x2.
// ---------------------------------------------------------------------------
__global__ __launch_bounds__(256) void proj_kernel(const float* __restrict__ x,
                                                   const float* __restrict__ w,
                                                   const float* __restrict__ b,
                                                   float* __restrict__ out) {
    __shared__ float sW[IND * H];   // 19.2 KB linear
    __shared__ float sA[64 * IND];  // 19.2 KB linear
    for (int i = threadIdx.x; i < IND * H / 4; i += 256)
        *(float4*)&sW[i * 4] = *(const float4*)&w[i * 4];

    const int lane = threadIdx.x & 31, wid = threadIdx.x >> 5;
    const int nl = lane & 3, cg = lane >> 2;
    const int ln0 = (wid << 3) + (nl << 1), ln1 = ln0 + 1;
    const float4 bb0 = *(const float4*)&b[cg * 8];
    const float4 bb1 = *(const float4*)&b[cg * 8 + 4];
    const int ntiles = (NN + 63) / 64;

    for (int tile = blockIdx.x; tile < ntiles; tile += gridDim.x) {
        const int nbase = tile * 64;
        const int valid = (nbase + 64 <= NN) ? 64 : (NN - nbase);
        const int cnt4 = valid * IND / 4;
        __syncthreads();
        for (int i = threadIdx.x; i < cnt4; i += 256)
            *(float4*)&sA[i * 4] = *(const float4*)(x + (size_t)nbase * IND + i * 4);
        __syncthreads();

        u64t a0c[4] = {pk2(bb0.x, bb0.y), pk2(bb0.z, bb0.w),
                       pk2(bb1.x, bb1.y), pk2(bb1.z, bb1.w)};
        u64t a1c[4] = {a0c[0], a0c[1], a0c[2], a0c[3]};
#pragma unroll 5
        for (int k = 0; k < IND; k++) {
            const ulonglong2 w0 = *(const ulonglong2*)&sW[k * H + cg * 8];
            const ulonglong2 w1 = *(const ulonglong2*)&sW[k * H + cg * 8 + 4];
            const float a0 = sA[ln0 * IND + k];
            const float a1 = sA[ln1 * IND + k];
            const u64t aa0 = pk2(a0, a0), aa1 = pk2(a1, a1);
            a0c[0] = fma2(aa0, w0.x, a0c[0]); a0c[1] = fma2(aa0, w0.y, a0c[1]);
            a0c[2] = fma2(aa0, w1.x, a0c[2]); a0c[3] = fma2(aa0, w1.y, a0c[3]);
            a1c[0] = fma2(aa1, w0.x, a1c[0]); a1c[1] = fma2(aa1, w0.y, a1c[1]);
            a1c[2] = fma2(aa1, w1.x, a1c[2]); a1c[3] = fma2(aa1, w1.y, a1c[3]);
        }
#pragma unroll
        for (int n = 0; n < 2; n++) {
            const int gn = nbase + ((n == 0) ? ln0 : ln1);
            if (gn >= NN) continue;
            const u64t* ac = (n == 0) ? a0c : a1c;
            float f0, f1, f2, f3, f4, f5, f6, f7;
            upk2(ac[0], f0, f1); upk2(ac[1], f2, f3);
            upk2(ac[2], f4, f5); upk2(ac[3], f6, f7);
            float* op = out + (size_t)gn * H + cg * 8;
            *(float4*)op       = make_float4(f0, f1, f2, f3);
            *(float4*)(op + 4) = make_float4(f4, f5, f6, f7);
        }
    }
}

// ---------------------------------------------------------------------------
// pk v4 (even/odd K-pairs): P(fp16) = h @ W2h(64x64) + b2, zero agg.
// ---------------------------------------------------------------------------
__global__ __launch_bounds__(256) void pk_kernel(const float* __restrict__ h,
                                                 const float* __restrict__ w,
                                                 const float* __restrict__ b,
                                                 __half* __restrict__ P,
                                                 float* __restrict__ agg) {
    __shared__ float sW2[(H / 2) * 128];  // 16 KB pair-packed
    __shared__ float sA[64 * 64];         // 16 KB, swizzled
    for (int i = threadIdx.x; i < H * H; i += 256)
        sW2[wpair_idx(i >> 6, i & 63)] = w[i];

    const int lane = threadIdx.x & 31, wid = threadIdx.x >> 5;
    const int nl = lane & 3, cg = lane >> 2;
    const int ln0 = (wid << 3) + (nl << 1), ln1 = ln0 + 1;
    const int sw0 = (ln0 & 7) * 4, sw1 = (ln1 & 7) * 4;
    float bias[8];
#pragma unroll
    for (int c = 0; c < 8; c++) bias[c] = b[cg * 8 + c];

    const int snd = threadIdx.x >> 2, sq = threadIdx.x & 3;
    const int ntiles = (NN + 63) / 64;
    const float4 z4 = make_float4(0.f, 0.f, 0.f, 0.f);

    for (int tile = blockIdx.x; tile < ntiles; tile += gridDim.x) {
        const int nbase = tile * 64;
        __syncthreads();
        {
            const int gn = nbase + snd;
            const int ssw = (snd & 7) * 4;
            if (gn < NN) {
#pragma unroll
                for (int j = 0; j < 4; j++) {
                    const int kk = sq * 16 + j * 4;
                    float4 v = *(const float4*)(h + (size_t)gn * H + kk);
                    *(float4*)&sA[snd * 64 + (kk ^ ssw)] = v;
                }
            } else {
#pragma unroll
                for (int j = 0; j < 4; j++)
                    *(float4*)&sA[snd * 64 + ((sq * 16 + j * 4) ^ ssw)] = z4;
            }
        }
        __syncthreads();

        u64t acc0[8], acc1[8];
#pragma unroll
        for (int c = 0; c < 8; c++) {
            acc0[c] = pk2(bias[c], 0.f);
            acc1[c] = pk2(bias[c], 0.f);
        }
#pragma unroll 8
        for (int kp = 0; kp < H / 2; kp++) {
            const float* wr = &sW2[kp * 128 + cg * 4];
            const ulonglong2 wa = *(const ulonglong2*)(wr);
            const ulonglong2 wb = *(const ulonglong2*)(wr + 32);
            const ulonglong2 wc = *(const ulonglong2*)(wr + 64);
            const ulonglong2 wd = *(const ulonglong2*)(wr + 96);
            const u64t ap0 = *(const u64t*)&sA[ln0 * 64 + ((2 * kp) ^ sw0)];
            const u64t ap1 = *(const u64t*)&sA[ln1 * 64 + ((2 * kp) ^ sw1)];
            acc0[0] = fma2(ap0, wa.x, acc0[0]); acc0[1] = fma2(ap0, wa.y, acc0[1]);
            acc0[2] = fma2(ap0, wb.x, acc0[2]); acc0[3] = fma2(ap0, wb.y, acc0[3]);
            acc0[4] = fma2(ap0, wc.x, acc0[4]); acc0[5] = fma2(ap0, wc.y, acc0[5]);
            acc0[6] = fma2(ap0, wd.x, acc0[6]); acc0[7] = fma2(ap0, wd.y, acc0[7]);
            acc1[0] = fma2(ap1, wa.x, acc1[0]); acc1[1] = fma2(ap1, wa.y, acc1[1]);
            acc1[2] = fma2(ap1, wb.x, acc1[2]); acc1[3] = fma2(ap1, wb.y, acc1[3]);
            acc1[4] = fma2(ap1, wc.x, acc1[4]); acc1[5] = fma2(ap1, wc.y, acc1[5]);
            acc1[6] = fma2(ap1, wd.x, acc1[6]); acc1[7] = fma2(ap1, wd.y, acc1[7]);
        }
#pragma unroll
        for (int n = 0; n < 2; n++) {
            const int gn = nbase + ((n == 0) ? ln0 : ln1);
            if (gn >= NN) continue;
            const u64t* ac = (n == 0) ? acc0 : acc1;
            float f[8];
#pragma unroll
            for (int c = 0; c < 8; c++) {
                float lo, hi; upk2(ac[c], lo, hi); f[c] = lo + hi;
            }
            __half2 p0 = __floats2half2_rn(f[0], f[1]);
            __half2 p1 = __floats2half2_rn(f[2], f[3]);
            __half2 p2 = __floats2half2_rn(f[4], f[5]);
            __half2 p3 = __floats2half2_rn(f[6], f[7]);
            uint4 pr;
            pr.x = *(unsigned*)&p0; pr.y = *(unsigned*)&p1;
            pr.z = *(unsigned*)&p2; pr.w = *(unsigned*)&p3;
            *(uint4*)(P + (size_t)gn * H + cg * 8) = pr;
        }
#pragma unroll
        for (int j = 0; j < 4; j++) {
            const int f = threadIdx.x * 4 + j;
            const int node = nbase + (f >> 4);
            if (node < NN)
                *((float4*)(agg + (size_t)nbase * H) + f) = z4;
        }
    }
}

// ---------------------------------------------------------------------------
// edge (R14 + staging pipeline): warp = 16 edges; eats tile for t+1 is
// prefetched into a register BEFORE the scatter of tile t, hiding the staging
// LDG latency behind the scatter's dependent chain.
// ---------------------------------------------------------------------------
__global__ __launch_bounds__(256) void edge_kernel(const int* __restrict__ esrc,
                                                   const int* __restrict__ edst,
                                                   const __half* __restrict__ eat16,
                                                   const float* __restrict__ w2e,
                                                   const __half* __restrict__ P,
                                                   float* __restrict__ agg) {
    __shared__ __half sW[HB * H];              // 2048 B
    __shared__ __half sA[8][HB * HB];          // 8 x 512 B
    __shared__ float  sB[8][HB * H];           // 8 x 4096 B

    for (int i = threadIdx.x; i < HB * H; i += 256) sW[i] = __float2half(w2e[i]);
    __syncthreads();

    const int lane = threadIdx.x & 31, wid = threadIdx.x >> 5;
    const int half = lane >> 4, hl = lane & 15;
    const int cbase = hl * 4;

    wmma::fragment<wmma::matrix_b, 16, 16, 16, __half, wmma::row_major> fw[4];
#pragma unroll
    for (int nt = 0; nt < 4; nt++)
        wmma::load_matrix_sync(fw[nt], &sW[nt * 16], H);

    __half* const myA = sA[wid];
    float*  const myB = sB[wid];

    const int nw = gridDim.x * 8;
    const int NT = NE / 16;
    int t = blockIdx.x * 8 + wid;

    uint4 stage;
    if (t < NT)
        stage = *(const uint4*)(eat16 + (size_t)t * (HB * 16) + lane * 8);

    while (t < NT) {
        const int ebase = t * 16;
        *(uint4*)(myA + lane * 8) = stage;
        __syncwarp();

        wmma::fragment<wmma::matrix_a, 16, 16, 16, __half, wmma::row_major> fa;
        wmma::load_matrix_sync(fa, myA, HB);
#pragma unroll
        for (int nt = 0; nt < 4; nt++) {
            wmma::fragment<wmma::accumulator, 16, 16, 16, float> fc;
            wmma::fill_fragment(fc, 0.f);
            wmma::mma_sync(fc, fa, fw[nt], fc);
            wmma::store_matrix_sync(&myB[nt * 16], fc, H, wmma::mem_row_major);
        }
        __syncwarp();

        // prefetch next tile's eats while scattering this tile
        const int tn = t + nw;
        if (tn < NT)
            stage = *(const uint4*)(eat16 + (size_t)tn * (HB * 16) + lane * 8);

#pragma unroll
        for (int r = 0; r < 8; r++) {
            const int el = 2 * r + half;
            const int e = ebase + el;
            const int src = esrc[e];
            const int dst = edst[e];
            if ((unsigned)src >= NN || (unsigned)dst >= NN) continue;

            const float4 bv = *(const float4*)(myB + el * H + cbase);
            const uint2 praw = *(const uint2*)(P + (size_t)src * H + cbase);
            const float2 pa = __half22float2(*(const __half2*)&praw.x);
            const float2 pb = __half22float2(*(const __half2*)&praw.y);

            float m0 = pa.x + bv.x, m1 = pa.y + bv.y;
            float m2 = pb.x + bv.z, m3 = pb.y + bv.w;
            m0 = fmaxf(m0, 0.1f * m0);
            m1 = fmaxf(m1, 0.1f * m1);
            m2 = fmaxf(m2, 0.1f * m2);
            m3 = fmaxf(m3, 0.1f * m3);

            float* dp = agg + (size_t)dst * H + cbase;
            asm volatile("red.global.add.v4.f32 [%0], {%1, %2, %3, %4};"
                         :: "l"(dp), "f"(m0), "f"(m1), "f"(m2), "f"(m3)
                         : "memory");
        }
        __syncwarp();
        t = tn;
    }
}

// ---------------------------------------------------------------------------
// upd v4 (even/odd K-pairs): out = concat(h, agg) @ W1(128x64) + b1.
// ---------------------------------------------------------------------------
__global__ __launch_bounds__(256) void upd_kernel(const float* __restrict__ h,
                                                  const float* __restrict__ agg,
                                                  const float* __restrict__ w,
                                                  const float* __restrict__ b,
                                                  float* __restrict__ out) {
    __shared__ float sW2[H * 128];   // 32 KB pair-packed
    __shared__ float sA[64 * 64];    // 16 KB, swizzled
    for (int i = threadIdx.x; i < 2 * H * H; i += 256)
        sW2[wpair_idx(i >> 6, i & 63)] = w[i];

    const int lane = threadIdx.x & 31, wid = threadIdx.x >> 5;
    const int nl = lane & 3, cg = lane >> 2;
    const int ln0 = (wid << 3) + (nl << 1), ln1 = ln0 + 1;
    const int sw0 = (ln0 & 7) * 4, sw1 = (ln1 & 7) * 4;
    float bias[8];
#pragma unroll
    for (int c = 0; c < 8; c++) bias[c] = b[cg * 8 + c];

    const int snd = threadIdx.x >> 2, sq = threadIdx.x & 3;
    const int ntiles = (NN + 63) / 64;
    const float4 z4 = make_float4(0.f, 0.f, 0.f, 0.f);

    for (int tile = blockIdx.x; tile < ntiles; tile += gridDim.x) {
        const int nbase = tile * 64;
        u64t acc0[8], acc1[8];
#pragma unroll
        for (int c = 0; c < 8; c++) {
            acc0[c] = pk2(bias[c], 0.f);
            acc1[c] = pk2(bias[c], 0.f);
        }

#pragma unroll
        for (int ch = 0; ch < 2; ch++) {
            const float* srcm = (ch == 0) ? h : agg;
            __syncthreads();
            {
                const int gn = nbase + snd;
                const int ssw = (snd & 7) * 4;
                if (gn < NN) {
#pragma unroll
                    for (int j = 0; j < 4; j++) {
                        const int kk = sq * 16 + j * 4;
                        float4 v = *(const float4*)(srcm + (size_t)gn * H + kk);
                        *(float4*)&sA[snd * 64 + (kk ^ ssw)] = v;
                    }
                } else {
#pragma unroll
                    for (int j = 0; j < 4; j++)
                        *(float4*)&sA[snd * 64 + ((sq * 16 + j * 4) ^ ssw)] = z4;
                }
            }
            __syncthreads();

            const float* wbase = &sW2[(ch * (H / 2)) * 128 + cg * 4];
#pragma unroll 8
            for (int kp = 0; kp < H / 2; kp++) {
                const float* wr = wbase + kp * 128;
                const ulonglong2 wa = *(const ulonglong2*)(wr);
                const ulonglong2 wb = *(const ulonglong2*)(wr + 32);
                const ulonglong2 wc = *(const ulonglong2*)(wr + 64);
                const ulonglong2 wd = *(const ulonglong2*)(wr + 96);
                const u64t ap0 = *(const u64t*)&sA[ln0 * 64 + ((2 * kp) ^ sw0)];
                const u64t ap1 = *(const u64t*)&sA[ln1 * 64 + ((2 * kp) ^ sw1)];
                acc0[0] = fma2(ap0, wa.x, acc0[0]); acc0[1] = fma2(ap0, wa.y, acc0[1]);
                acc0[2] = fma2(ap0, wb.x, acc0[2]); acc0[3] = fma2(ap0, wb.y, acc0[3]);
                acc0[4] = fma2(ap0, wc.x, acc0[4]); acc0[5] = fma2(ap0, wc.y, acc0[5]);
                acc0[6] = fma2(ap0, wd.x, acc0[6]); acc0[7] = fma2(ap0, wd.y, acc0[7]);
                acc1[0] = fma2(ap1, wa.x, acc1[0]); acc1[1] = fma2(ap1, wa.y, acc1[1]);
                acc1[2] = fma2(ap1, wb.x, acc1[2]); acc1[3] = fma2(ap1, wb.y, acc1[3]);
                acc1[4] = fma2(ap1, wc.x, acc1[4]); acc1[5] = fma2(ap1, wc.y, acc1[5]);
                acc1[6] = fma2(ap1, wd.x, acc1[6]); acc1[7] = fma2(ap1, wd.y, acc1[7]);
            }
        }

#pragma unroll
        for (int n = 0; n < 2; n++) {
            const int gn = nbase + ((n == 0) ? ln0 : ln1);
            if (gn >= NN) continue;
            const u64t* ac = (n == 0) ? acc0 : acc1;
            float f[8];
#pragma unroll
            for (int c = 0; c < 8; c++) {
                float lo, hi; upk2(ac[c], lo, hi); f[c] = lo + hi;
            }
            float* op = out + (size_t)gn * H + cg * 8;
            *(float4*)op       = make_float4(f[0], f[1], f[2], f[3]);
            *(float4*)(op + 4) = make_float4(f[4], f[5], f[6], f[7]);
        }
    }
}

// ---------------------------------------------------------------------------
extern "C" void kernel_launch(void* const* d_in, const int* in_sizes, int n_in,
                              void* d_out, int out_size) {
    const float* x      = (const float*)d_in[0];   // [100000, 75]
    const int*   eidx   = (const int*)d_in[1];     // [2, 1600000] (int64 -> int32)
    const float* eattr  = (const float*)d_in[2];   // [1600000, 16]
    const float* proj_w = (const float*)d_in[3];
    const float* proj_b = (const float*)d_in[4];
    const float* u2w    = (const float*)d_in[5];   // [3, 80, 64]
    const float* u2b    = (const float*)d_in[6];
    const float* u1w    = (const float*)d_in[7];   // [3, 128, 64]
    const float* u1b    = (const float*)d_in[8];
    float*       out    = (float*)d_out;           // [100000, 64]

    float *hA, *hB, *agg;
    __half *P, *eat16;
    cudaGetSymbolAddress((void**)&hA, g_hA);
    cudaGetSymbolAddress((void**)&hB, g_hB);
    cudaGetSymbolAddress((void**)&P, g_P);
    cudaGetSymbolAddress((void**)&agg, g_agg);
    cudaGetSymbolAddress((void**)&eat16, g_eat16);

    cvt_kernel<<<(NE * HB / 8 + 255) / 256, 256>>>(eattr, eat16);
    proj_kernel<<<592, 256>>>(x, proj_w, proj_b, hA);

    for (int l = 0; l < 3; l++) {
        const float* hin = (l == 1) ? hB : hA;          // l0:A, l1:B, l2:A
        float* hout = (l == 0) ? hB : ((l == 1) ? hA : out);
        const float* w2 = u2w + (size_t)l * 80 * 64;     // rows 0..63 = W2h, 64..79 = W2e
        pk_kernel<<<592, 256>>>(hin, w2, u2b + l * 64, P, agg);
        edge_kernel<<<1184, 256>>>(eidx, eidx + NE, eat16, w2 + 64 * 64, P, agg);
        upd_kernel<<<592, 256>>>(hin, agg, u1w + (size_t)l * 128 * 64, u1b + l * 64, hout);
    }
}